// round 1
// baseline (speedup 1.0000x reference)
#include <cuda_runtime.h>

#define BB 2048
#define TT 500
#define NN 64
#define ROWS (BB*TT)

// Scratch: summed+scaled retinal drive, stored transposed [t][b] for coalesced scan reads.
__device__ float g_S1[ROWS];
__device__ float g_S2[ROWS];

__device__ __forceinline__ float fm(float a, float b) { return __fmul_rn(a, b); }
__device__ __forceinline__ float fa(float a, float b) { return __fadd_rn(a, b); }
__device__ __forceinline__ float fs(float a, float b) { return __fsub_rn(a, b); }

// ---------------------------------------------------------------------------
// Kernel 1: zp1[b,t] = sum_n(input[b,t,n]*w0), zp2 = sum_n(input*w12)
// Warp handles 2 rows (2 x 64 floats = 32 float4) per iteration, fully coalesced.
// Balanced binary tree sum (products first, matching reference order).
// ---------------------------------------------------------------------------
__global__ void reduce_kernel(const float4* __restrict__ in4, const float* __restrict__ w) {
    const float w0 = w[0], w12 = w[12];
    int gtid   = blockIdx.x * blockDim.x + threadIdx.x;
    int warp   = gtid >> 5;
    int lane   = threadIdx.x & 31;
    int nwarps = (gridDim.x * blockDim.x) >> 5;
    int half   = lane >> 4;  // which row of the pair this lane contributes to

    for (int p = warp; p < ROWS / 2; p += nwarps) {
        float4 x = in4[p * 32 + lane];
        float s1 = fa(fa(fm(x.x, w0),  fm(x.y, w0)),  fa(fm(x.z, w0),  fm(x.w, w0)));
        float s2 = fa(fa(fm(x.x, w12), fm(x.y, w12)), fa(fm(x.z, w12), fm(x.w, w12)));
#pragma unroll
        for (int off = 1; off < 16; off <<= 1) {
            s1 = fa(s1, __shfl_xor_sync(0xffffffffu, s1, off));
            s2 = fa(s2, __shfl_xor_sync(0xffffffffu, s2, off));
        }
        if ((lane & 15) == 0) {
            int row = p * 2 + half;       // row = b*T + t
            int b = row / TT;
            int t = row - b * TT;
            g_S1[t * BB + b] = s1;
            g_S2[t * BB + b] = s2;
        }
    }
}

// ---------------------------------------------------------------------------
// Izhikevich Euler step, exact expression order of the reference:
//   v_ = v + 0.25*((((0.04*v)*v + 5.0*v) + 140.0) - u + I)
//   u_ = u + (DT*a)*(b*v - u)          (DT*a = 0.005 for all neuron types)
//   z  = v_ >= 30 ;  v <- z? c : v_ ;  u <- u_ + z*d
// No FMA contraction (__f*_rn) to match non-contracted reference arithmetic.
// ---------------------------------------------------------------------------
__device__ __forceinline__ float izh(float& v, float& u, float I,
                                     float bpar, float c, float d) {
    float acc = fa(fa(fm(fm(0.04f, v), v), fm(5.0f, v)), 140.0f);
    acc = fa(fs(acc, u), I);
    float v_ = fa(v, fm(0.25f, acc));
    float u_ = fa(u, fm(0.005f, fs(fm(bpar, v), u)));
    bool z = (v_ >= 30.0f);
    v = z ? c : v_;
    u = z ? fa(u_, d) : u_;
    return z ? 1.0f : 0.0f;
}

// ---------------------------------------------------------------------------
// Kernel 2: sequential scan over T. One thread per batch element.
// Channel-2 IFN neuron is dead state (feeds no output) and is skipped.
// ---------------------------------------------------------------------------
__global__ void scan_kernel(const float* __restrict__ w, float* __restrict__ out) {
    int b = blockIdx.x * blockDim.x + threadIdx.x;
    if (b >= BB) return;

    const float w1 = w[1],  w2 = w[2],   w3 = w[3],   w4 = w[4],  w5 = w[5];
    const float w6 = w[6],  w8 = w[8],   w9 = w[9],   w10 = w[10], w11 = w[11];
    const float w13 = w[13], w16 = w[16], w17 = w[17], w20 = w[20], w23 = w[23];

    // channel 1 state
    float vL = -70.f, uL = -14.f, zL = 0.f;
    float vE = -64.f, uE = -16.f;
    float vI = -64.f, uI = -16.f;
    float vT = -70.f, uT = -14.f, zT = 0.f;
    float vM = -64.f, uM = -16.f;
    // channel 2 state (IFN omitted: unobservable)
    float vL2 = -70.f, uL2 = -14.f, zL2 = 0.f;
    float vE2 = -64.f, uE2 = -16.f;
    float vT2 = -70.f, uT2 = -14.f, zT2 = 0.f;
    float vM2 = -64.f, uM2 = -16.f;

    float*  o0 = out;                       // o_spikes  (z6)   [B,T]
    float*  o1 = out + (size_t)ROWS;        // v         (vM)   [B,T]
    float*  o2 = out + (size_t)2 * ROWS;    // o_spikes2 (z62)  [B,T]
    float*  o3 = out + (size_t)3 * ROWS;    // v2        (vM2)  [B,T]
    float4* o4 = (float4*)(out + (size_t)4 * ROWS);  // o_spikes_o [B,T,4]
    float4* o5 = (float4*)(out + (size_t)8 * ROWS);  // v_o        [B,T,4]

    for (int t = 0; t < TT; t++) {
        float zp  = g_S1[t * BB + b];
        float zp2 = g_S2[t * BB + b];

        // --- channel 1 ---
        float z2 = izh(vL, uL, fa(fm(w2, fm(zp, w1)), fm(w3, zL)), 0.20f, -65.f, 6.f);
        float z3 = izh(vE, uE, fa(fm(zp, w4), fm(z2, w5)),          0.25f, -55.f, 0.05f);
        float z4 = izh(vI, uI, fm(z3, w6),                           0.25f, -65.f, 6.f);
        float z5 = izh(vT, uT, fa(fm(w9, fm(z3, w8)), fm(w10, zT)), 0.20f, -50.f, 2.f);
        float z6 = izh(vM, uM, fm(z5, w11),                          0.25f, -65.f, 6.f);
        zL = z2; zT = z5;

        // --- channel 2 ---
        float z22 = izh(vL2, uL2, fa(fm(w2, fm(zp2, w13)), fm(w3, zL2)), 0.20f, -65.f, 6.f);
        float z32 = izh(vE2, uE2, fa(fm(zp2, w16), fm(z22, w17)),         0.25f, -55.f, 0.05f);
        float z52 = izh(vT2, uT2, fa(fm(w9, fm(z32, w20)), fm(w10, zT2)), 0.20f, -50.f, 2.f);
        float z62 = izh(vM2, uM2, fm(z52, w23),                            0.25f, -65.f, 6.f);
        zL2 = z22; zT2 = z52;

        int idx = b * TT + t;
        o0[idx] = z6;
        o1[idx] = vM;
        o2[idx] = z62;
        o3[idx] = vM2;
        o4[idx] = make_float4(z2, z3, z4, z5);
        o5[idx] = make_float4(vL, vE, vI, vT);
    }
}

extern "C" void kernel_launch(void* const* d_in, const int* in_sizes, int n_in,
                              void* d_out, int out_size) {
    const float4* in4 = (const float4*)d_in[0];   // input_mat [B,T,N] fp32
    const float*  w   = (const float*)d_in[1];    // weights_matrix [24] fp32
    float*        out = (float*)d_out;

    // 2000 blocks x 256 threads = 16000 warps; 512000 row-pairs -> 32 iters/warp
    reduce_kernel<<<2000, 256>>>(in4, w);
    // 2048 lanes, one warp per block to spread across SMs
    scan_kernel<<<64, 32>>>(w, out);
}